// round 17
// baseline (speedup 1.0000x reference)
#include <cuda_runtime.h>
#include <math.h>

// B=1024, NL=64, W=2048; inner scan = 62 layers.
#define TMM_B   1024
#define TMM_NL  64
#define TMM_W   2048
#define TMM_NI  62
#define TMM_BPB 2          // batches per block (R15: 4 -> 2 for occupancy)
#define TWO_PI  6.283185307179586f
#define EPS_N   1e-8f
#define EPS_Y   1e-9f

// R15: SFU-bound (MUFU 4/layer @ rt8 = 32 cyc/warp-layer floor ~= 55us).
// R13 hit 68us at occ 54% (grid 1024 = 6.9 blocks/SM). Changes:
//  - BPB=2 -> grid 2048 blocks -> ~7 resident blocks/SM, occ ~85%
//  - smem pre-splatted float2 {n,n} / {-inv,-inv}: LDS.64 lands directly in
//    packed-operand reg pairs, deleting 4 ALU pack-MOVs per layer
//  - retains chain-packed f32x2 accumulators (10 packed ops/layer) and
//    one-layer trig prefetch

typedef unsigned long long u64;

__device__ __forceinline__ u64 pk2(float lo, float hi) {
    u64 r; asm("mov.b64 %0, {%1, %2};" : "=l"(r) : "f"(lo), "f"(hi)); return r;
}
__device__ __forceinline__ void upk2(u64 v, float& lo, float& hi) {
    asm("mov.b64 {%0, %1}, %2;" : "=f"(lo), "=f"(hi) : "l"(v));
}
__device__ __forceinline__ u64 mul2(u64 a, u64 b) {
    u64 r; asm("mul.rn.f32x2 %0, %1, %2;" : "=l"(r) : "l"(a), "l"(b)); return r;
}
__device__ __forceinline__ u64 fma2(u64 a, u64 b, u64 c) {
    u64 r; asm("fma.rn.f32x2 %0, %1, %2, %3;" : "=l"(r) : "l"(a), "l"(b), "l"(c)); return r;
}

__device__ __forceinline__ float tmm_epilogue(float A, float C, float Bv, float D,
                                              float nin, float nsub)
{
    const float Ae = A + EPS_Y;
    const float t1 = nin * Ae;          // Re(n_in*(E+eps))
    const float t2 = D * nsub;          // Re(H)
    const float t3 = nin * Bv * nsub;   // Im(n_in*(E+eps)); Im(H)=C
    const float nr = t1 - t2;
    const float ni = t3 - C;
    const float dr = t1 + t2;
    const float di = t3 + C;
    return fmaf(nr, nr, ni * ni) / fmaf(dr, dr, di * di);
}

__global__ __launch_bounds__(256)
void tmm_kernel(const float* __restrict__ n_layers,
                const float* __restrict__ d_layers,
                const float* __restrict__ wavelengths,
                float* __restrict__ out)
{
    __shared__ float  s_nd[TMM_BPB][TMM_NI];   // n*d
    __shared__ float2 s_nn[TMM_BPB][TMM_NI];   // {n, n}
    __shared__ float2 s_mi[TMM_BPB][TMM_NI];   // {-1/(n+e), -1/(n+e)}
    __shared__ float2 s_e [TMM_BPB];           // {n_in, n_sub}

    const int tid = threadIdx.x;
    const int w0  = blockIdx.x * 256 + tid;     // 0..1023
    const int w1  = w0 + (TMM_W / 2);           // 1024..2047
    const int b0  = blockIdx.y * TMM_BPB;

    for (int idx = tid; idx < TMM_BPB * TMM_NI; idx += 256) {
        const int bb = idx / TMM_NI;
        const int i  = idx % TMM_NI;
        const float* nrow = n_layers + (size_t)(b0 + bb) * TMM_NL;
        const float* drow = d_layers + (size_t)(b0 + bb) * TMM_NL;
        const float ni  = nrow[i + 1];
        const float di  = drow[i + 1];
        const float miv = -1.0f / (ni + EPS_N);
        s_nd[bb][i] = ni * di;
        s_nn[bb][i] = make_float2(ni, ni);
        s_mi[bb][i] = make_float2(miv, miv);
    }
    if (tid < TMM_BPB) {
        const float* nrow = n_layers + (size_t)(b0 + tid) * TMM_NL;
        s_e[tid] = make_float2(nrow[0], nrow[TMM_NL - 1]);
    }
    __syncthreads();

    const float k0a = TWO_PI / wavelengths[w0];
    const float k0b = TWO_PI / wavelengths[w1];

    #pragma unroll 1
    for (int bb = 0; bb < TMM_BPB; bb++) {
        const float*  nd_p = s_nd[bb];
        const u64*    nn_p = (const u64*)s_nn[bb];
        const u64*    mi_p = (const u64*)s_mi[bb];

        u64 A  = pk2(1.0f, 1.0f);   // lanes = (chain a, chain b)
        u64 Bv = pk2(0.0f, 0.0f);
        u64 Cn = pk2(0.0f, 0.0f);   // Cn = -C
        u64 D  = pk2(1.0f, 1.0f);

        // Prologue: layer-0 trig in flight.
        float sa, ca, sb, cb;
        {
            const float nd0 = nd_p[0];
            __sincosf(nd0 * k0a, &sa, &ca);
            __sincosf(nd0 * k0b, &sb, &cb);
        }

        #pragma unroll 2
        for (int i = 0; i < TMM_NI - 1; i++) {
            // Prefetch layer i+1 trig (independent of recurrence).
            const float ndn = nd_p[i + 1];
            float sa_n, ca_n, sb_n, cb_n;
            __sincosf(ndn * k0a, &sa_n, &ca_n);
            __sincosf(ndn * k0b, &sb_n, &cb_n);

            // Consume layer i. LDS.64 -> packed operands directly.
            const u64 nn = nn_p[i];
            const u64 mi = mi_p[i];
            const u64 sp = pk2(sa, sb);
            const u64 cp = pk2(ca, cb);

            const u64 ns = mul2(sp, nn);    // ( n*s)  per chain
            const u64 mv = mul2(sp, mi);    // (-s*inv) per chain
            const u64 An = fma2(Bv, ns, mul2(A,  cp));
            const u64 Bn = fma2(A,  mv, mul2(Bv, cp));
            const u64 Cx = fma2(D,  ns, mul2(Cn, cp));
            const u64 Dn = fma2(Cn, mv, mul2(D,  cp));
            A = An; Bv = Bn; Cn = Cx; D = Dn;

            sa = sa_n; ca = ca_n; sb = sb_n; cb = cb_n;
        }
        // Peeled last layer.
        {
            const u64 nn = nn_p[TMM_NI - 1];
            const u64 mi = mi_p[TMM_NI - 1];
            const u64 sp = pk2(sa, sb);
            const u64 cp = pk2(ca, cb);
            const u64 ns = mul2(sp, nn);
            const u64 mv = mul2(sp, mi);
            const u64 An = fma2(Bv, ns, mul2(A,  cp));
            const u64 Bn = fma2(A,  mv, mul2(Bv, cp));
            const u64 Cx = fma2(D,  ns, mul2(Cn, cp));
            const u64 Dn = fma2(Cn, mv, mul2(D,  cp));
            A = An; Bv = Bn; Cn = Cx; D = Dn;
        }

        const float2 e = s_e[bb];
        float Aa, Ab, Ba, Bb, Ca_, Cb_, Da, Db;
        upk2(A,  Aa, Ab);
        upk2(Bv, Ba, Bb);
        upk2(Cn, Ca_, Cb_);
        upk2(D,  Da, Db);

        const float R0 = tmm_epilogue(Aa, -Ca_, Ba, Da, e.x, e.y);
        const float R1 = tmm_epilogue(Ab, -Cb_, Bb, Db, e.x, e.y);

        float* orow = out + (size_t)(b0 + bb) * TMM_W;
        orow[w0] = R0;
        orow[w1] = R1;
    }
}

extern "C" void kernel_launch(void* const* d_in, const int* in_sizes, int n_in,
                              void* d_out, int out_size)
{
    const float* n_layers    = (const float*)d_in[0];
    const float* d_layers    = (const float*)d_in[1];
    const float* wavelengths = (const float*)d_in[2];
    float* out = (float*)d_out;

    dim3 block(256);
    dim3 grid((TMM_W / 2) / 256, TMM_B / TMM_BPB);   // (4, 512)
    tmm_kernel<<<grid, block>>>(n_layers, d_layers, wavelengths, out);
}